// round 1
// baseline (speedup 1.0000x reference)
#include <cuda_runtime.h>
#include <cstdint>

// ---------------- scratch (device globals; no allocations allowed) ----------
__device__ float g_b1[(size_t)64*128*128*32];   // enc1 out  NHWC [64,128,128,32]
__device__ float g_b2[(size_t)64*64*64*64];     // enc2 out  NHWC [64,64,64,64]
__device__ float g_q [(size_t)64*64*64*16];     // quantized NHWC [64,64,64,16]
__device__ float g_d1[(size_t)64*128*128*64];   // dec1 out  NHWC [64,128,128,64]
__device__ float g_d2[(size_t)64*256*256*32];   // dec2 out  NHWC [64,256,256,32]

__device__ float g_wr1 [864];     // enc1 w  [kh][kw][ci=3][co=32]
__device__ float g_wr2 [18432];   // enc2 w  [kh][kw][ci=32][co=64]
__device__ float g_wrd1[9216];    // dec1 w  [kh][kw][ci=16][co=64]
__device__ float g_wrd2[18432];   // dec2 w  [kh][kw][ci=64][co=32]
__device__ float g_wrd3[864];     // dec3 w  [kh][kw][ci=32][co=3] (pre-flipped)
__device__ double g_acc[2];       // [0]=vq sq-sum, [1]=recon sq-sum

// ---------------- helpers ---------------------------------------------------
__device__ __forceinline__ float blockReduceSum(float v){
  __shared__ float red[32];
  #pragma unroll
  for (int o=16;o;o>>=1) v += __shfl_down_sync(0xffffffffu, v, o);
  int lane = threadIdx.x & 31, w = threadIdx.x >> 5;
  if (lane==0) red[w]=v;
  __syncthreads();
  if (w==0){
    v = (lane < ((int)blockDim.x>>5)) ? red[lane] : 0.f;
    #pragma unroll
    for (int o=16;o;o>>=1) v += __shfl_down_sync(0xffffffffu, v, o);
  }
  return v;
}

// ---------------- weight repack + accumulator reset -------------------------
__global__ void repack_k(const float* __restrict__ ew1, const float* __restrict__ ew2,
                         const float* __restrict__ dw1, const float* __restrict__ dw2,
                         const float* __restrict__ dw3){
  int t = blockIdx.x*blockDim.x + threadIdx.x;
  int nt = gridDim.x*blockDim.x;
  if (blockIdx.x==0 && threadIdx.x<2) g_acc[threadIdx.x]=0.0;
  // enc1: [co=32][ci=3][3][3] -> [kh][kw][ci][co]
  for (int i=t;i<864;i+=nt){ int co=i%32; int r=i/32; int ci=r%3; r/=3; int kw=r%3, kh=r/3;
    g_wr1[i] = ew1[((co*3+ci)*3+kh)*3+kw]; }
  // enc2: [64][32][3][3] -> [kh][kw][32][64]
  for (int i=t;i<18432;i+=nt){ int co=i&63; int r=i>>6; int ci=r%32; r/=32; int kw=r%3, kh=r/3;
    g_wr2[i] = ew2[((co*32+ci)*3+kh)*3+kw]; }
  // dec1: [ci=16][co=64][3][3] -> [kh][kw][16][64]
  for (int i=t;i<9216;i+=nt){ int co=i&63; int r=i>>6; int ci=r%16; r/=16; int kw=r%3, kh=r/3;
    g_wrd1[i] = dw1[((ci*64+co)*3+kh)*3+kw]; }
  // dec2: [ci=64][co=32][3][3] -> [kh][kw][64][32]
  for (int i=t;i<18432;i+=nt){ int co=i&31; int r=i>>5; int ci=r%64; r/=64; int kw=r%3, kh=r/3;
    g_wrd2[i] = dw2[((ci*32+co)*3+kh)*3+kw]; }
  // dec3: [ci=32][co=3][3][3] -> [kh][kw][32][3] with (2-kh,2-kw) flip baked in
  for (int i=t;i<864;i+=nt){ int co=i%3; int r=i/3; int ci=r%32; r/=32; int kw=r%3, kh=r/3;
    g_wrd3[i] = dw3[((ci*3+co)*3+(2-kh))*3+(2-kw)]; }
}

// ---------------- enc1: 3->32, k3 s2 p1, relu; x NCHW -> g_b1 NHWC ----------
__global__ void enc1_k(const float* __restrict__ x, const float* __restrict__ bias){
  __shared__ float ws[864];
  __shared__ float bs[32];
  int tid = threadIdx.x;
  for (int i=tid;i<864;i+=256) ws[i]=g_wr1[i];
  if (tid<32) bs[tid]=bias[tid];
  __syncthreads();
  int idx = blockIdx.x*256 + tid;                 // 64*128*128 = 1048576
  int wo = idx & 127, ho = (idx>>7)&127, b = idx>>14;
  float acc[32];
  #pragma unroll
  for (int c=0;c<32;c++) acc[c]=bs[c];
  const float* xb = x + (size_t)b*3*65536;
  for (int kh=0;kh<3;kh++){
    int hi = 2*ho-1+kh; if ((unsigned)hi>=256u) continue;
    for (int kw=0;kw<3;kw++){
      int wi = 2*wo-1+kw; if ((unsigned)wi>=256u) continue;
      #pragma unroll
      for (int ci=0;ci<3;ci++){
        float v = xb[(size_t)ci*65536 + hi*256 + wi];
        const float* w = &ws[((kh*3+kw)*3+ci)*32];
        #pragma unroll
        for (int c=0;c<32;c++) acc[c]=fmaf(v,w[c],acc[c]);
      }
    }
  }
  float4* op = (float4*)(g_b1 + (size_t)idx*32);
  #pragma unroll
  for (int c4=0;c4<8;c4++){
    float4 o; o.x=fmaxf(acc[c4*4+0],0.f); o.y=fmaxf(acc[c4*4+1],0.f);
    o.z=fmaxf(acc[c4*4+2],0.f); o.w=fmaxf(acc[c4*4+3],0.f);
    op[c4]=o;
  }
}

// ---------------- enc2: 32->64, k3 s2 p1, relu (co split in halves) ---------
__global__ void enc2_k(const float* __restrict__ bias){
  __shared__ float ws[9216];   // [tap][ci=32][co_local=32]
  __shared__ float bs[32];
  int half = blockIdx.y;
  int tid = threadIdx.x;
  for (int i=tid;i<9216;i+=256){
    int c = i & 31; int r = i >> 5;               // r = tap*32+ci
    ws[i] = g_wr2[r*64 + half*32 + c];
  }
  if (tid<32) bs[tid]=bias[half*32+tid];
  __syncthreads();
  int idx = blockIdx.x*256 + tid;                 // 64*64*64 = 262144
  int wo = idx & 63, ho = (idx>>6)&63, b = idx>>12;
  float acc[32];
  #pragma unroll
  for (int c=0;c<32;c++) acc[c]=bs[c];
  for (int kh=0;kh<3;kh++){
    int hi = 2*ho-1+kh; if ((unsigned)hi>=128u) continue;
    for (int kw=0;kw<3;kw++){
      int wi = 2*wo-1+kw; if ((unsigned)wi>=128u) continue;
      const float4* ip = (const float4*)(g_b1 + ((size_t)((b*128+hi)*128+wi))*32);
      const float* wt = &ws[(kh*3+kw)*1024];
      #pragma unroll 4
      for (int ci4=0;ci4<8;ci4++){
        float4 v = ip[ci4];
        const float* w0 = wt + ci4*128;
        #pragma unroll
        for (int c=0;c<32;c++) acc[c]=fmaf(v.x,w0[c],acc[c]);
        #pragma unroll
        for (int c=0;c<32;c++) acc[c]=fmaf(v.y,w0[32+c],acc[c]);
        #pragma unroll
        for (int c=0;c<32;c++) acc[c]=fmaf(v.z,w0[64+c],acc[c]);
        #pragma unroll
        for (int c=0;c<32;c++) acc[c]=fmaf(v.w,w0[96+c],acc[c]);
      }
    }
  }
  float4* op = (float4*)(g_b2 + (size_t)idx*64 + half*32);
  #pragma unroll
  for (int c4=0;c4<8;c4++){
    float4 o; o.x=fmaxf(acc[c4*4+0],0.f); o.y=fmaxf(acc[c4*4+1],0.f);
    o.z=fmaxf(acc[c4*4+2],0.f); o.w=fmaxf(acc[c4*4+3],0.f);
    op[c4]=o;
  }
}

// ------------- enc3 (1x1 64->16) + VQ + quantize + VQ loss ------------------
__global__ void vq_k(const float* __restrict__ cb, const float* __restrict__ w3,
                     const float* __restrict__ b3){
  __shared__ float cbs[8192];   // [512][16]
  __shared__ float nrm[512];    // 0.5*||e||^2
  __shared__ float w3s[1024];   // [d=16][ci=64]
  __shared__ float b3s[16];
  int tid = threadIdx.x;
  for (int i=tid;i<8192;i+=256) cbs[i]=cb[i];
  for (int i=tid;i<1024;i+=256) w3s[i]=w3[i];
  if (tid<16) b3s[tid]=b3[tid];
  __syncthreads();
  for (int k=tid;k<512;k+=256){
    float s=0.f;
    #pragma unroll
    for (int d=0;d<16;d++){ float e=cbs[k*16+d]; s=fmaf(e,e,s); }
    nrm[k]=0.5f*s;
  }
  __syncthreads();
  int idx = blockIdx.x*256 + tid;                 // 262144
  float z[16];
  #pragma unroll
  for (int d=0;d<16;d++) z[d]=b3s[d];
  const float4* ip = (const float4*)(g_b2 + (size_t)idx*64);
  #pragma unroll 4
  for (int ci4=0;ci4<16;ci4++){
    float4 v = ip[ci4];
    #pragma unroll
    for (int d=0;d<16;d++){
      const float* w = &w3s[d*64 + ci4*4];
      z[d] = fmaf(v.x,w[0], fmaf(v.y,w[1], fmaf(v.z,w[2], fmaf(v.w,w[3], z[d]))));
    }
  }
  int best=0; float bests=-3.4e38f;
  for (int k=0;k<512;k++){
    float s = -nrm[k];
    const float* e = &cbs[k*16];
    #pragma unroll
    for (int d=0;d<16;d++) s = fmaf(z[d], e[d], s);
    if (s>bests){ bests=s; best=k; }              // first winner == argmin tie-break
  }
  const float* e = &cbs[best*16];
  float ls=0.f;
  float4* qo = (float4*)(g_q + (size_t)idx*16);
  #pragma unroll
  for (int d4=0;d4<4;d4++){
    float4 o; o.x=e[d4*4+0]; o.y=e[d4*4+1]; o.z=e[d4*4+2]; o.w=e[d4*4+3];
    qo[d4]=o;
    #pragma unroll
    for (int c=0;c<4;c++){ float d=e[d4*4+c]-z[d4*4+c]; ls=fmaf(d,d,ls); }
  }
  float s = blockReduceSum(ls);
  if (tid==0) atomicAdd(&g_acc[0], (double)s);
}

// ------------- dec1: convT 16->64 k3 s2 p1 op1, relu ------------------------
__global__ void dec1_k(const float* __restrict__ bias){
  __shared__ float ws[9216];   // [tap][ci=16][co=64]
  __shared__ float bs[64];
  int tid = threadIdx.x;
  for (int i=tid;i<9216;i+=256) ws[i]=g_wrd1[i];
  if (tid<64) bs[tid]=bias[tid];
  __syncthreads();
  int idx = blockIdx.x*256 + tid;                 // 64*128*128
  int wo = idx & 127, ho = (idx>>7)&127, b = idx>>14;
  float acc[64];
  #pragma unroll
  for (int c=0;c<64;c++) acc[c]=bs[c];
  for (int kh=0;kh<3;kh++){
    int t = ho+1-kh; if (t & 1) continue;
    int hi = t >> 1; if ((unsigned)hi>=64u) continue;
    for (int kw=0;kw<3;kw++){
      int t2 = wo+1-kw; if (t2 & 1) continue;
      int wi = t2 >> 1; if ((unsigned)wi>=64u) continue;
      const float4* ip = (const float4*)(g_q + ((size_t)((b*64+hi)*64+wi))*16);
      const float* wt = &ws[(kh*3+kw)*1024];
      #pragma unroll
      for (int ci4=0;ci4<4;ci4++){
        float4 v = ip[ci4];
        const float* w0 = wt + ci4*256;
        #pragma unroll
        for (int c=0;c<64;c++) acc[c]=fmaf(v.x,w0[c],acc[c]);
        #pragma unroll
        for (int c=0;c<64;c++) acc[c]=fmaf(v.y,w0[64+c],acc[c]);
        #pragma unroll
        for (int c=0;c<64;c++) acc[c]=fmaf(v.z,w0[128+c],acc[c]);
        #pragma unroll
        for (int c=0;c<64;c++) acc[c]=fmaf(v.w,w0[192+c],acc[c]);
      }
    }
  }
  float4* op = (float4*)(g_d1 + (size_t)idx*64);
  #pragma unroll
  for (int c4=0;c4<16;c4++){
    float4 o; o.x=fmaxf(acc[c4*4+0],0.f); o.y=fmaxf(acc[c4*4+1],0.f);
    o.z=fmaxf(acc[c4*4+2],0.f); o.w=fmaxf(acc[c4*4+3],0.f);
    op[c4]=o;
  }
}

// ------------- dec2: convT 64->32 k3 s2 p1 op1, relu (parity-templated) -----
template<int PH,int PW>
__global__ void dec2_k(const float* __restrict__ bias){
  constexpr int NKH = PH?2:1, NKW = PW?2:1;
  __shared__ float ws[NKH*NKW*2048];   // [tap][ci=64][co=32]
  __shared__ float bs[32];
  int tid = threadIdx.x;
  for (int i=tid;i<NKH*NKW*2048;i+=256){
    int j = i & 2047; int t = i >> 11;
    int a = t / NKW, c = t % NKW;
    int kh = PH ? a*2 : 1;
    int kw = PW ? c*2 : 1;
    ws[i] = g_wrd2[(kh*3+kw)*2048 + j];
  }
  if (tid<32) bs[tid]=bias[tid];
  __syncthreads();
  int idx = blockIdx.x*256 + tid;                 // 64*128*128 per class
  int wb = idx & 127, hb = (idx>>7)&127, b = idx>>14;
  int ho = 2*hb+PH, wo = 2*wb+PW;
  float acc[32];
  #pragma unroll
  for (int c=0;c<32;c++) acc[c]=bs[c];
  #pragma unroll
  for (int a=0;a<NKH;a++){
    int kh = PH ? a*2 : 1;
    int hi = (ho+1-kh) >> 1; if ((unsigned)hi>=128u) continue;
    #pragma unroll
    for (int cc=0;cc<NKW;cc++){
      int kw = PW ? cc*2 : 1;
      int wi = (wo+1-kw) >> 1; if ((unsigned)wi>=128u) continue;
      const float4* ip = (const float4*)(g_d1 + ((size_t)((b*128+hi)*128+wi))*64);
      const float* wt = &ws[(a*NKW+cc)*2048];
      #pragma unroll 4
      for (int ci4=0;ci4<16;ci4++){
        float4 v = ip[ci4];
        const float* w0 = wt + ci4*128;
        #pragma unroll
        for (int c=0;c<32;c++) acc[c]=fmaf(v.x,w0[c],acc[c]);
        #pragma unroll
        for (int c=0;c<32;c++) acc[c]=fmaf(v.y,w0[32+c],acc[c]);
        #pragma unroll
        for (int c=0;c<32;c++) acc[c]=fmaf(v.z,w0[64+c],acc[c]);
        #pragma unroll
        for (int c=0;c<32;c++) acc[c]=fmaf(v.w,w0[96+c],acc[c]);
      }
    }
  }
  float4* op = (float4*)(g_d2 + ((size_t)((b*256+ho)*256+wo))*32);
  #pragma unroll
  for (int c4=0;c4<8;c4++){
    float4 o; o.x=fmaxf(acc[c4*4+0],0.f); o.y=fmaxf(acc[c4*4+1],0.f);
    o.z=fmaxf(acc[c4*4+2],0.f); o.w=fmaxf(acc[c4*4+3],0.f);
    op[c4]=o;
  }
}

// ------------- dec3: convT 32->3 k3 s1 p1 + recon MSE (fused, no store) -----
#define COMPSEL(v,c) ((c)==0 ? (v).x : (c)==1 ? (v).y : (c)==2 ? (v).z : (v).w)
__global__ void dec3_k(const float* __restrict__ x, const float* __restrict__ bias){
  __shared__ float ws[864];    // [kh][kw][ci=32][co=3]
  __shared__ float bs[3];
  int tid = threadIdx.x;
  for (int i=tid;i<864;i+=256) ws[i]=g_wrd3[i];
  if (tid<3) bs[tid]=bias[tid];
  __syncthreads();
  int idx = blockIdx.x*256 + tid;                 // 64*256*64 (4 pixels/thread in w)
  int tw = idx & 63, ho = (idx>>6)&255, b = idx>>14;
  int wo0 = tw*4;
  float acc[4][3];
  #pragma unroll
  for (int o=0;o<4;o++){ acc[o][0]=bs[0]; acc[o][1]=bs[1]; acc[o][2]=bs[2]; }
  for (int kh=0;kh<3;kh++){
    int hi = ho-1+kh; if ((unsigned)hi>=256u) continue;
    const float* rowp = g_d2 + ((size_t)(b*256+hi))*256*32;
    #pragma unroll 2
    for (int ci4=0;ci4<8;ci4++){
      float4 v[6];
      #pragma unroll
      for (int j=0;j<6;j++){
        int wi = wo0-1+j;
        if ((unsigned)wi<256u) v[j] = ((const float4*)(rowp + (size_t)wi*32))[ci4];
        else { v[j].x=0.f; v[j].y=0.f; v[j].z=0.f; v[j].w=0.f; }
      }
      #pragma unroll
      for (int kw=0;kw<3;kw++){
        #pragma unroll
        for (int c=0;c<4;c++){
          int ci = ci4*4+c;
          const float* w = &ws[((kh*3+kw)*32+ci)*3];
          float w0=w[0], w1=w[1], w2=w[2];
          #pragma unroll
          for (int o=0;o<4;o++){
            float val = COMPSEL(v[o+kw], c);
            acc[o][0]=fmaf(val,w0,acc[o][0]);
            acc[o][1]=fmaf(val,w1,acc[o][1]);
            acc[o][2]=fmaf(val,w2,acc[o][2]);
          }
        }
      }
    }
  }
  float ls=0.f;
  const float* xb = x + (size_t)b*3*65536;
  #pragma unroll
  for (int o=0;o<4;o++){
    #pragma unroll
    for (int c=0;c<3;c++){
      float d = acc[o][c] - xb[(size_t)c*65536 + ho*256 + wo0+o];
      ls = fmaf(d,d,ls);
    }
  }
  float s = blockReduceSum(ls);
  if (tid==0) atomicAdd(&g_acc[1], (double)s);
}

// ------------- finalize -----------------------------------------------------
__global__ void final_k(float* __restrict__ out){
  double vq  = g_acc[0];
  double rec = g_acc[1];
  float e_q  = (float)(1.25 * vq / 4194304.0);          // (1+0.25)*mean, N=64*64*64*16
  float mse  = (float)(rec / 12582912.0);               // N=64*3*256*256
  out[0] = e_q;
  out[1] = mse;   // recon_loss = mse / DATA_VARIANCE(=1)
  out[2] = mse;   // recon_mse
}

// ---------------- launch ----------------------------------------------------
extern "C" void kernel_launch(void* const* d_in, const int* in_sizes, int n_in,
                              void* d_out, int out_size){
  const float* x   = (const float*)d_in[0];
  const float* ew1 = (const float*)d_in[1];
  const float* eb1 = (const float*)d_in[2];
  const float* ew2 = (const float*)d_in[3];
  const float* eb2 = (const float*)d_in[4];
  const float* ew3 = (const float*)d_in[5];
  const float* eb3 = (const float*)d_in[6];
  const float* cb  = (const float*)d_in[7];
  const float* dw1 = (const float*)d_in[8];
  const float* db1 = (const float*)d_in[9];
  const float* dw2 = (const float*)d_in[10];
  const float* db2 = (const float*)d_in[11];
  const float* dw3 = (const float*)d_in[12];
  const float* db3 = (const float*)d_in[13];
  float* out = (float*)d_out;

  repack_k<<<64,256>>>(ew1, ew2, dw1, dw2, dw3);
  enc1_k<<<4096,256>>>(x, eb1);
  enc2_k<<<dim3(1024,2),256>>>(eb2);
  vq_k<<<1024,256>>>(cb, ew3, eb3);
  dec1_k<<<4096,256>>>(db1);
  dec2_k<0,0><<<4096,256>>>(db2);
  dec2_k<0,1><<<4096,256>>>(db2);
  dec2_k<1,0><<<4096,256>>>(db2);
  dec2_k<1,1><<<4096,256>>>(db2);
  dec3_k<<<4096,256>>>(x, db3);
  final_k<<<1,1>>>(out);
}

// round 2
// speedup vs baseline: 1.6449x; 1.6449x over previous
#include <cuda_runtime.h>
#include <cstdint>

typedef unsigned long long u64;

// ---------------- scratch (device globals; no allocations allowed) ----------
__device__ float g_b1[(size_t)64*128*128*32];   // enc1 out  NHWC [64,128,128,32]
__device__ float g_b2[(size_t)64*64*64*64];     // enc2 out  NHWC [64,64,64,64]
__device__ float g_q [(size_t)64*64*64*16];     // quantized NHWC [64,64,64,16]
__device__ float g_d1[(size_t)64*128*128*64];   // dec1 out  NHWC [64,128,128,64]
__device__ float g_d2[(size_t)64*256*256*32];   // dec2 out  NHWC [64,256,256,32]

__device__ float g_wr1 [864];     // enc1 w  [kh][kw][ci=3][co=32]
__device__ float g_wr2 [18432];   // enc2 w  [kh][kw][ci=32][co=64]
__device__ float g_wrd1[9216];    // dec1 w  [kh][kw][ci=16][co=64]
__device__ float g_wrd2[18432];   // dec2 w  [kh][kw][ci=64][co=32]
__device__ float g_wrd3[864];     // dec3 w  [kh][kw][ci=32][co=3] (pre-flipped)
__device__ double g_acc[2];       // [0]=vq sq-sum, [1]=recon sq-sum

// ---------------- f32x2 helpers ---------------------------------------------
__device__ __forceinline__ u64 pack2(float lo, float hi){
  u64 r; asm("mov.b64 %0, {%1, %2};" : "=l"(r)
             : "r"(__float_as_uint(lo)), "r"(__float_as_uint(hi)));
  return r;
}
__device__ __forceinline__ u64 bcast2(float v){
  u64 r; asm("mov.b64 %0, {%1, %1};" : "=l"(r) : "r"(__float_as_uint(v)));
  return r;
}
__device__ __forceinline__ float2 unpack2(u64 p){
  unsigned lo, hi;
  asm("mov.b64 {%0, %1}, %2;" : "=r"(lo), "=r"(hi) : "l"(p));
  return make_float2(__uint_as_float(lo), __uint_as_float(hi));
}
__device__ __forceinline__ void ffma2(u64 &acc, u64 a, u64 b){
  asm("fma.rn.f32x2 %0, %1, %2, %0;" : "+l"(acc) : "l"(a), "l"(b));
}

__device__ __forceinline__ float blockReduceSum(float v){
  __shared__ float red[32];
  #pragma unroll
  for (int o=16;o;o>>=1) v += __shfl_down_sync(0xffffffffu, v, o);
  int lane = threadIdx.x & 31, w = threadIdx.x >> 5;
  if (lane==0) red[w]=v;
  __syncthreads();
  if (w==0){
    v = (lane < ((int)blockDim.x>>5)) ? red[lane] : 0.f;
    #pragma unroll
    for (int o=16;o;o>>=1) v += __shfl_down_sync(0xffffffffu, v, o);
  }
  return v;
}

// ---------------- weight repack + accumulator reset -------------------------
__global__ void repack_k(const float* __restrict__ ew1, const float* __restrict__ ew2,
                         const float* __restrict__ dw1, const float* __restrict__ dw2,
                         const float* __restrict__ dw3){
  int t = blockIdx.x*blockDim.x + threadIdx.x;
  int nt = gridDim.x*blockDim.x;
  if (blockIdx.x==0 && threadIdx.x<2) g_acc[threadIdx.x]=0.0;
  for (int i=t;i<864;i+=nt){ int co=i%32; int r=i/32; int ci=r%3; r/=3; int kw=r%3, kh=r/3;
    g_wr1[i] = ew1[((co*3+ci)*3+kh)*3+kw]; }
  for (int i=t;i<18432;i+=nt){ int co=i&63; int r=i>>6; int ci=r%32; r/=32; int kw=r%3, kh=r/3;
    g_wr2[i] = ew2[((co*32+ci)*3+kh)*3+kw]; }
  for (int i=t;i<9216;i+=nt){ int co=i&63; int r=i>>6; int ci=r%16; r/=16; int kw=r%3, kh=r/3;
    g_wrd1[i] = dw1[((ci*64+co)*3+kh)*3+kw]; }
  for (int i=t;i<18432;i+=nt){ int co=i&31; int r=i>>5; int ci=r%64; r/=64; int kw=r%3, kh=r/3;
    g_wrd2[i] = dw2[((ci*32+co)*3+kh)*3+kw]; }
  for (int i=t;i<864;i+=nt){ int co=i%3; int r=i/3; int ci=r%32; r/=32; int kw=r%3, kh=r/3;
    g_wrd3[i] = dw3[((ci*3+co)*3+(2-kh))*3+(2-kw)]; }
}

// ---------------- enc1: 3->32, k3 s2 p1, relu; x NCHW -> g_b1 NHWC ----------
__global__ __launch_bounds__(256) void enc1_k(const float* __restrict__ x,
                                              const float* __restrict__ bias){
  __shared__ __align__(16) float ws[864];
  __shared__ float bs[32];
  int tid = threadIdx.x;
  for (int i=tid;i<864;i+=256) ws[i]=g_wr1[i];
  if (tid<32) bs[tid]=bias[tid];
  __syncthreads();
  int idx = blockIdx.x*256 + tid;
  int wo = idx & 127, ho = (idx>>7)&127, b = idx>>14;
  u64 acc[16];
  #pragma unroll
  for (int c=0;c<16;c++) acc[c]=pack2(bs[2*c],bs[2*c+1]);
  const float* xb = x + (size_t)b*3*65536;
  for (int kh=0;kh<3;kh++){
    int hi = 2*ho-1+kh; if ((unsigned)hi>=256u) continue;
    for (int kw=0;kw<3;kw++){
      int wi = 2*wo-1+kw; if ((unsigned)wi>=256u) continue;
      #pragma unroll
      for (int ci=0;ci<3;ci++){
        u64 v = bcast2(xb[(size_t)ci*65536 + hi*256 + wi]);
        const ulonglong2* wp = (const ulonglong2*)&ws[((kh*3+kw)*3+ci)*32];
        #pragma unroll
        for (int q=0;q<8;q++){ ulonglong2 t=wp[q]; ffma2(acc[2*q],v,t.x); ffma2(acc[2*q+1],v,t.y); }
      }
    }
  }
  float4* op = (float4*)(g_b1 + (size_t)idx*32);
  #pragma unroll
  for (int c4=0;c4<8;c4++){
    float2 a=unpack2(acc[2*c4]), b2=unpack2(acc[2*c4+1]);
    float4 o; o.x=fmaxf(a.x,0.f); o.y=fmaxf(a.y,0.f); o.z=fmaxf(b2.x,0.f); o.w=fmaxf(b2.y,0.f);
    op[c4]=o;
  }
}

// ---------------- enc2: 32->64, k3 s2 p1, relu (co split in halves) ---------
__global__ __launch_bounds__(256) void enc2_k(const float* __restrict__ bias){
  __shared__ __align__(16) float ws[9216];   // [tap][ci=32][co_local=32]
  __shared__ float bs[32];
  int half = blockIdx.y;
  int tid = threadIdx.x;
  for (int i=tid;i<9216;i+=256){
    int c = i & 31; int r = i >> 5;
    ws[i] = g_wr2[r*64 + half*32 + c];
  }
  if (tid<32) bs[tid]=bias[half*32+tid];
  __syncthreads();
  int idx = blockIdx.x*256 + tid;
  int wo = idx & 63, ho = (idx>>6)&63, b = idx>>12;
  u64 acc[16];
  #pragma unroll
  for (int c=0;c<16;c++) acc[c]=pack2(bs[2*c],bs[2*c+1]);
  for (int kh=0;kh<3;kh++){
    int hi = 2*ho-1+kh; if ((unsigned)hi>=128u) continue;
    for (int kw=0;kw<3;kw++){
      int wi = 2*wo-1+kw; if ((unsigned)wi>=128u) continue;
      const float4* ip = (const float4*)(g_b1 + ((size_t)((b*128+hi)*128+wi))*32);
      const float* wt = &ws[(kh*3+kw)*1024];
      #pragma unroll 4
      for (int ci4=0;ci4<8;ci4++){
        float4 v = ip[ci4];
        u64 vx=bcast2(v.x), vy=bcast2(v.y), vz=bcast2(v.z), vw=bcast2(v.w);
        const ulonglong2* wp = (const ulonglong2*)(wt + ci4*128);
        #pragma unroll
        for (int q=0;q<8;q++){ ulonglong2 t=wp[q];    ffma2(acc[2*q],vx,t.x); ffma2(acc[2*q+1],vx,t.y); }
        #pragma unroll
        for (int q=0;q<8;q++){ ulonglong2 t=wp[8+q];  ffma2(acc[2*q],vy,t.x); ffma2(acc[2*q+1],vy,t.y); }
        #pragma unroll
        for (int q=0;q<8;q++){ ulonglong2 t=wp[16+q]; ffma2(acc[2*q],vz,t.x); ffma2(acc[2*q+1],vz,t.y); }
        #pragma unroll
        for (int q=0;q<8;q++){ ulonglong2 t=wp[24+q]; ffma2(acc[2*q],vw,t.x); ffma2(acc[2*q+1],vw,t.y); }
      }
    }
  }
  float4* op = (float4*)(g_b2 + (size_t)idx*64 + half*32);
  #pragma unroll
  for (int c4=0;c4<8;c4++){
    float2 a=unpack2(acc[2*c4]), b2=unpack2(acc[2*c4+1]);
    float4 o; o.x=fmaxf(a.x,0.f); o.y=fmaxf(a.y,0.f); o.z=fmaxf(b2.x,0.f); o.w=fmaxf(b2.y,0.f);
    op[c4]=o;
  }
}

// ------------- enc3 (1x1 64->16) + VQ + quantize + VQ loss ------------------
__global__ __launch_bounds__(256) void vq_k(const float* __restrict__ cb,
                                            const float* __restrict__ w3,
                                            const float* __restrict__ b3){
  __shared__ __align__(16) float cbs[8192];   // [512][16]
  __shared__ float nrm[512];                   // 0.5*||e||^2
  __shared__ __align__(16) float w3s[1024];    // [ci=64][d=16]
  __shared__ float b3s[16];
  int tid = threadIdx.x;
  for (int i=tid;i<8192;i+=256) cbs[i]=cb[i];
  for (int i=tid;i<1024;i+=256){ int ci=i>>4, d=i&15; w3s[i]=w3[d*64+ci]; }
  if (tid<16) b3s[tid]=b3[tid];
  __syncthreads();
  for (int k=tid;k<512;k+=256){
    float s=0.f;
    #pragma unroll
    for (int d=0;d<16;d++){ float e=cbs[k*16+d]; s=fmaf(e,e,s); }
    nrm[k]=0.5f*s;
  }
  __syncthreads();
  int idx = blockIdx.x*256 + tid;
  u64 z2[8];
  #pragma unroll
  for (int q=0;q<8;q++) z2[q]=pack2(b3s[2*q],b3s[2*q+1]);
  const float4* ip = (const float4*)(g_b2 + (size_t)idx*64);
  #pragma unroll 4
  for (int ci4=0;ci4<16;ci4++){
    float4 v = ip[ci4];
    float vv[4]={v.x,v.y,v.z,v.w};
    #pragma unroll
    for (int j=0;j<4;j++){
      u64 vb = bcast2(vv[j]);
      const ulonglong2* wp = (const ulonglong2*)&w3s[(ci4*4+j)*16];
      #pragma unroll
      for (int q=0;q<4;q++){ ulonglong2 t=wp[q]; ffma2(z2[2*q],vb,t.x); ffma2(z2[2*q+1],vb,t.y); }
    }
  }
  float z[16];
  #pragma unroll
  for (int q=0;q<8;q++){ float2 p=unpack2(z2[q]); z[2*q]=p.x; z[2*q+1]=p.y; }
  int best=0; float bests=-3.4e38f;
  for (int k=0;k<512;k++){
    u64 s2 = 0ull;
    const ulonglong2* e2 = (const ulonglong2*)&cbs[k*16];
    #pragma unroll
    for (int q=0;q<4;q++){ ulonglong2 t=e2[q]; ffma2(s2,z2[2*q],t.x); ffma2(s2,z2[2*q+1],t.y); }
    float2 p=unpack2(s2);
    float s = p.x + p.y - nrm[k];
    if (s>bests){ bests=s; best=k; }              // first winner == argmin tie-break
  }
  const float* e = &cbs[best*16];
  float ls=0.f;
  float4* qo = (float4*)(g_q + (size_t)idx*16);
  #pragma unroll
  for (int d4=0;d4<4;d4++){
    float4 o; o.x=e[d4*4+0]; o.y=e[d4*4+1]; o.z=e[d4*4+2]; o.w=e[d4*4+3];
    qo[d4]=o;
    #pragma unroll
    for (int c=0;c<4;c++){ float d=e[d4*4+c]-z[d4*4+c]; ls=fmaf(d,d,ls); }
  }
  float s = blockReduceSum(ls);
  if (tid==0) atomicAdd(&g_acc[0], (double)s);
}

// ------------- dec1: convT 16->64 k3 s2 p1 op1, relu ------------------------
__global__ __launch_bounds__(256) void dec1_k(const float* __restrict__ bias){
  __shared__ __align__(16) float ws[9216];   // [tap][ci=16][co=64]
  __shared__ float bs[64];
  int tid = threadIdx.x;
  for (int i=tid;i<9216;i+=256) ws[i]=g_wrd1[i];
  if (tid<64) bs[tid]=bias[tid];
  __syncthreads();
  int idx = blockIdx.x*256 + tid;
  int wo = idx & 127, ho = (idx>>7)&127, b = idx>>14;
  u64 acc[32];
  #pragma unroll
  for (int c=0;c<32;c++) acc[c]=pack2(bs[2*c],bs[2*c+1]);
  for (int kh=0;kh<3;kh++){
    int t = ho+1-kh; if (t & 1) continue;
    int hi = t >> 1; if ((unsigned)hi>=64u) continue;
    for (int kw=0;kw<3;kw++){
      int t2 = wo+1-kw; if (t2 & 1) continue;
      int wi = t2 >> 1; if ((unsigned)wi>=64u) continue;
      const float4* ip = (const float4*)(g_q + ((size_t)((b*64+hi)*64+wi))*16);
      const float* wt = &ws[(kh*3+kw)*1024];
      #pragma unroll
      for (int ci4=0;ci4<4;ci4++){
        float4 v = ip[ci4];
        float vv[4]={v.x,v.y,v.z,v.w};
        #pragma unroll
        for (int j=0;j<4;j++){
          u64 vb = bcast2(vv[j]);
          const ulonglong2* wp = (const ulonglong2*)(wt + ci4*256 + j*64);
          #pragma unroll
          for (int q=0;q<16;q++){ ulonglong2 t3=wp[q]; ffma2(acc[2*q],vb,t3.x); ffma2(acc[2*q+1],vb,t3.y); }
        }
      }
    }
  }
  float4* op = (float4*)(g_d1 + (size_t)idx*64);
  #pragma unroll
  for (int c4=0;c4<16;c4++){
    float2 a=unpack2(acc[2*c4]), b2=unpack2(acc[2*c4+1]);
    float4 o; o.x=fmaxf(a.x,0.f); o.y=fmaxf(a.y,0.f); o.z=fmaxf(b2.x,0.f); o.w=fmaxf(b2.y,0.f);
    op[c4]=o;
  }
}

// ------------- dec2: convT 64->32 k3 s2 p1 op1, relu (parity-templated) -----
template<int PH,int PW>
__global__ __launch_bounds__(256) void dec2_k(const float* __restrict__ bias){
  constexpr int NKH = PH?2:1, NKW = PW?2:1;
  __shared__ __align__(16) float ws[NKH*NKW*2048];   // [tap][ci=64][co=32]
  __shared__ float bs[32];
  int tid = threadIdx.x;
  for (int i=tid;i<NKH*NKW*2048;i+=256){
    int j = i & 2047; int t = i >> 11;
    int a = t / NKW, c = t % NKW;
    int kh = PH ? a*2 : 1;
    int kw = PW ? c*2 : 1;
    ws[i] = g_wrd2[(kh*3+kw)*2048 + j];
  }
  if (tid<32) bs[tid]=bias[tid];
  __syncthreads();
  int idx = blockIdx.x*256 + tid;
  int wb = idx & 127, hb = (idx>>7)&127, b = idx>>14;
  int ho = 2*hb+PH, wo = 2*wb+PW;
  u64 acc[16];
  #pragma unroll
  for (int c=0;c<16;c++) acc[c]=pack2(bs[2*c],bs[2*c+1]);
  #pragma unroll
  for (int a=0;a<NKH;a++){
    int kh = PH ? a*2 : 1;
    int hi = (ho+1-kh) >> 1; if ((unsigned)hi>=128u) continue;
    #pragma unroll
    for (int cc=0;cc<NKW;cc++){
      int kw = PW ? cc*2 : 1;
      int wi = (wo+1-kw) >> 1; if ((unsigned)wi>=128u) continue;
      const float4* ip = (const float4*)(g_d1 + ((size_t)((b*128+hi)*128+wi))*64);
      const float* wt = &ws[(a*NKW+cc)*2048];
      #pragma unroll 4
      for (int ci4=0;ci4<16;ci4++){
        float4 v = ip[ci4];
        u64 vx=bcast2(v.x), vy=bcast2(v.y), vz=bcast2(v.z), vw=bcast2(v.w);
        const ulonglong2* wp = (const ulonglong2*)(wt + ci4*128);
        #pragma unroll
        for (int q=0;q<8;q++){ ulonglong2 t=wp[q];    ffma2(acc[2*q],vx,t.x); ffma2(acc[2*q+1],vx,t.y); }
        #pragma unroll
        for (int q=0;q<8;q++){ ulonglong2 t=wp[8+q];  ffma2(acc[2*q],vy,t.x); ffma2(acc[2*q+1],vy,t.y); }
        #pragma unroll
        for (int q=0;q<8;q++){ ulonglong2 t=wp[16+q]; ffma2(acc[2*q],vz,t.x); ffma2(acc[2*q+1],vz,t.y); }
        #pragma unroll
        for (int q=0;q<8;q++){ ulonglong2 t=wp[24+q]; ffma2(acc[2*q],vw,t.x); ffma2(acc[2*q+1],vw,t.y); }
      }
    }
  }
  float4* op = (float4*)(g_d2 + ((size_t)((b*256+ho)*256+wo))*32);
  #pragma unroll
  for (int c4=0;c4<8;c4++){
    float2 a=unpack2(acc[2*c4]), b2=unpack2(acc[2*c4+1]);
    float4 o; o.x=fmaxf(a.x,0.f); o.y=fmaxf(a.y,0.f); o.z=fmaxf(b2.x,0.f); o.w=fmaxf(b2.y,0.f);
    op[c4]=o;
  }
}

// ------------- dec3: convT 32->3 k3 s1 p1 + recon MSE (fused, no store) -----
#define COMPSEL(v,c) ((c)==0 ? (v).x : (c)==1 ? (v).y : (c)==2 ? (v).z : (v).w)
__global__ __launch_bounds__(256) void dec3_k(const float* __restrict__ x,
                                              const float* __restrict__ bias){
  __shared__ __align__(16) u64 ws2[864];    // [kh][kw][ci=32][co=3], dup-pair {w,w}
  __shared__ float bs[3];
  int tid = threadIdx.x;
  for (int i=tid;i<864;i+=256){ float w=g_wrd3[i]; ws2[i]=pack2(w,w); }
  if (tid<3) bs[tid]=bias[tid];
  __syncthreads();
  int idx = blockIdx.x*256 + tid;                 // 64*256*64 (4 pixels/thread in w)
  int tw = idx & 63, ho = (idx>>6)&255, b = idx>>14;
  int wo0 = tw*4;
  u64 accp[3][2];   // [co][pixel-pair]: lane0=pix(2p), lane1=pix(2p+1)
  #pragma unroll
  for (int co=0;co<3;co++){ accp[co][0]=pack2(bs[co],bs[co]); accp[co][1]=accp[co][0]; }
  for (int kh=0;kh<3;kh++){
    int hi = ho-1+kh; if ((unsigned)hi>=256u) continue;
    const float* rowp = g_d2 + ((size_t)(b*256+hi))*256*32;
    #pragma unroll 2
    for (int ci4=0;ci4<8;ci4++){
      float4 v[6];
      #pragma unroll
      for (int j=0;j<6;j++){
        int wi = wo0-1+j;
        if ((unsigned)wi<256u) v[j] = ((const float4*)(rowp + (size_t)wi*32))[ci4];
        else { v[j].x=0.f; v[j].y=0.f; v[j].z=0.f; v[j].w=0.f; }
      }
      #pragma unroll
      for (int kw=0;kw<3;kw++){
        #pragma unroll
        for (int c=0;c<4;c++){
          float f0=COMPSEL(v[kw+0],c), f1=COMPSEL(v[kw+1],c);
          float f2=COMPSEL(v[kw+2],c), f3=COMPSEL(v[kw+3],c);
          u64 a0=pack2(f0,f1), a1=pack2(f2,f3);
          const u64* wd = &ws2[((kw*3 /*dummy*/ ,((kh*3+kw)*32 + ci4*4 + c)*3))];
          u64 w0=wd[0], w1=wd[1], w2=wd[2];
          ffma2(accp[0][0],a0,w0); ffma2(accp[0][1],a1,w0);
          ffma2(accp[1][0],a0,w1); ffma2(accp[1][1],a1,w1);
          ffma2(accp[2][0],a0,w2); ffma2(accp[2][1],a1,w2);
        }
      }
    }
  }
  float acc[4][3];
  #pragma unroll
  for (int co=0;co<3;co++){
    float2 p0=unpack2(accp[co][0]), p1=unpack2(accp[co][1]);
    acc[0][co]=p0.x; acc[1][co]=p0.y; acc[2][co]=p1.x; acc[3][co]=p1.y;
  }
  float ls=0.f;
  const float* xb = x + (size_t)b*3*65536;
  #pragma unroll
  for (int o=0;o<4;o++){
    #pragma unroll
    for (int c=0;c<3;c++){
      float d = acc[o][c] - xb[(size_t)c*65536 + ho*256 + wo0+o];
      ls = fmaf(d,d,ls);
    }
  }
  float s = blockReduceSum(ls);
  if (tid==0) atomicAdd(&g_acc[1], (double)s);
}

// ------------- finalize -----------------------------------------------------
__global__ void final_k(float* __restrict__ out){
  double vq  = g_acc[0];
  double rec = g_acc[1];
  float e_q  = (float)(1.25 * vq / 4194304.0);
  float mse  = (float)(rec / 12582912.0);
  out[0] = e_q;
  out[1] = mse;
  out[2] = mse;
}

// ---------------- launch ----------------------------------------------------
extern "C" void kernel_launch(void* const* d_in, const int* in_sizes, int n_in,
                              void* d_out, int out_size){
  const float* x   = (const float*)d_in[0];
  const float* ew1 = (const float*)d_in[1];
  const float* eb1 = (const float*)d_in[2];
  const float* ew2 = (const float*)d_in[3];
  const float* eb2 = (const float*)d_in[4];
  const float* ew3 = (const float*)d_in[5];
  const float* eb3 = (const float*)d_in[6];
  const float* cb  = (const float*)d_in[7];
  const float* dw1 = (const float*)d_in[8];
  const float* db1 = (const float*)d_in[9];
  const float* dw2 = (const float*)d_in[10];
  const float* db2 = (const float*)d_in[11];
  const float* dw3 = (const float*)d_in[12];
  const float* db3 = (const float*)d_in[13];
  float* out = (float*)d_out;

  repack_k<<<64,256>>>(ew1, ew2, dw1, dw2, dw3);
  enc1_k<<<4096,256>>>(x, eb1);
  enc2_k<<<dim3(1024,2),256>>>(eb2);
  vq_k<<<1024,256>>>(cb, ew3, eb3);
  dec1_k<<<4096,256>>>(db1);
  dec2_k<0,0><<<4096,256>>>(db2);
  dec2_k<0,1><<<4096,256>>>(db2);
  dec2_k<1,0><<<4096,256>>>(db2);
  dec2_k<1,1><<<4096,256>>>(db2);
  dec3_k<<<4096,256>>>(x, db3);
  final_k<<<1,1>>>(out);
}

// round 3
// speedup vs baseline: 2.0266x; 1.2320x over previous
#include <cuda_runtime.h>
#include <cstdint>

typedef unsigned long long u64;

// ---------------- scratch (device globals; no allocations allowed) ----------
__device__ float g_b1[(size_t)64*128*128*32];   // enc1 out  NHWC [64,128,128,32]
__device__ float g_b2[(size_t)64*64*64*64];     // enc2 out  NHWC [64,64,64,64]
__device__ float g_q [(size_t)64*64*64*16];     // quantized NHWC [64,64,64,16]
__device__ float g_d1[(size_t)64*128*128*64];   // dec1 out  NHWC [64,128,128,64]
__device__ float g_d2[(size_t)64*256*256*32];   // dec2 out  NHWC [64,256,256,32]

__device__ float g_wr1 [864];     // enc1 w  [kh][kw][ci=3][co=32]
__device__ float g_wr2 [18432];   // enc2 w  [kh][kw][ci=32][co=64]
__device__ float g_wrd1[9216];    // dec1 w  [kh][kw][ci=16][co=64]
__device__ float g_wrd2[18432];   // dec2 w  [kh][kw][ci=64][co=32]
__device__ float g_wrd3[864];     // dec3 w  [kh][kw][ci=32][co=3] (pre-flipped)
__device__ double g_acc[2];       // [0]=vq sq-sum, [1]=recon sq-sum

// ---------------- f32x2 helpers ---------------------------------------------
__device__ __forceinline__ u64 pack2(float lo, float hi){
  u64 r; asm("mov.b64 %0, {%1, %2};" : "=l"(r)
             : "r"(__float_as_uint(lo)), "r"(__float_as_uint(hi)));
  return r;
}
__device__ __forceinline__ u64 bcast2(float v){
  u64 r; asm("mov.b64 %0, {%1, %1};" : "=l"(r) : "r"(__float_as_uint(v)));
  return r;
}
__device__ __forceinline__ float2 unpack2(u64 p){
  unsigned lo, hi;
  asm("mov.b64 {%0, %1}, %2;" : "=r"(lo), "=r"(hi) : "l"(p));
  return make_float2(__uint_as_float(lo), __uint_as_float(hi));
}
__device__ __forceinline__ void ffma2(u64 &acc, u64 a, u64 b){
  asm("fma.rn.f32x2 %0, %1, %2, %0;" : "+l"(acc) : "l"(a), "l"(b));
}
__device__ __forceinline__ float4 zero4(){ float4 z; z.x=z.y=z.z=z.w=0.f; return z; }

__device__ __forceinline__ float blockReduceSum(float v){
  __shared__ float red[32];
  #pragma unroll
  for (int o=16;o;o>>=1) v += __shfl_down_sync(0xffffffffu, v, o);
  int lane = threadIdx.x & 31, w = threadIdx.x >> 5;
  if (lane==0) red[w]=v;
  __syncthreads();
  if (w==0){
    v = (lane < ((int)blockDim.x>>5)) ? red[lane] : 0.f;
    #pragma unroll
    for (int o=16;o;o>>=1) v += __shfl_down_sync(0xffffffffu, v, o);
  }
  return v;
}

// ---------------- weight repack + accumulator reset -------------------------
__global__ void repack_k(const float* __restrict__ ew1, const float* __restrict__ ew2,
                         const float* __restrict__ dw1, const float* __restrict__ dw2,
                         const float* __restrict__ dw3){
  int t = blockIdx.x*blockDim.x + threadIdx.x;
  int nt = gridDim.x*blockDim.x;
  if (blockIdx.x==0 && threadIdx.x<2) g_acc[threadIdx.x]=0.0;
  for (int i=t;i<864;i+=nt){ int co=i%32; int r=i/32; int ci=r%3; r/=3; int kw=r%3, kh=r/3;
    g_wr1[i] = ew1[((co*3+ci)*3+kh)*3+kw]; }
  for (int i=t;i<18432;i+=nt){ int co=i&63; int r=i>>6; int ci=r%32; r/=32; int kw=r%3, kh=r/3;
    g_wr2[i] = ew2[((co*32+ci)*3+kh)*3+kw]; }
  for (int i=t;i<9216;i+=nt){ int co=i&63; int r=i>>6; int ci=r%16; r/=16; int kw=r%3, kh=r/3;
    g_wrd1[i] = dw1[((ci*64+co)*3+kh)*3+kw]; }
  for (int i=t;i<18432;i+=nt){ int co=i&31; int r=i>>5; int ci=r%64; r/=64; int kw=r%3, kh=r/3;
    g_wrd2[i] = dw2[((ci*32+co)*3+kh)*3+kw]; }
  for (int i=t;i<864;i+=nt){ int co=i%3; int r=i/3; int ci=r%32; r/=32; int kw=r%3, kh=r/3;
    g_wrd3[i] = dw3[((ci*3+co)*3+(2-kh))*3+(2-kw)]; }
}

// ---------------- enc1: 3->32, k3 s2 p1, relu; 2 pixels/thread --------------
__global__ __launch_bounds__(256) void enc1_k(const float* __restrict__ x,
                                              const float* __restrict__ bias){
  __shared__ __align__(16) float ws[864];
  __shared__ float bs[32];
  int tid = threadIdx.x;
  for (int i=tid;i<864;i+=256) ws[i]=g_wr1[i];
  if (tid<32) bs[tid]=bias[tid];
  __syncthreads();
  int idx = blockIdx.x*256 + tid;                 // [0, 524288)
  int tw = idx & 63, ho = (idx>>6)&127, b = idx>>13;
  u64 acc[2][16];
  #pragma unroll
  for (int c=0;c<16;c++){ acc[0][c]=pack2(bs[2*c],bs[2*c+1]); acc[1][c]=acc[0][c]; }
  const float* xb = x + (size_t)b*3*65536;
  for (int kh=0;kh<3;kh++){
    int hi = 2*ho-1+kh; bool inh = (unsigned)hi<256u;
    for (int kw=0;kw<3;kw++){
      int wi0 = 4*tw-1+kw, wi1 = wi0+2;
      bool in0 = inh && (unsigned)wi0<256u;
      bool in1 = inh && (unsigned)wi1<256u;
      #pragma unroll
      for (int ci=0;ci<3;ci++){
        float f0 = in0 ? xb[(size_t)ci*65536 + hi*256 + wi0] : 0.f;
        float f1 = in1 ? xb[(size_t)ci*65536 + hi*256 + wi1] : 0.f;
        u64 v0=bcast2(f0), v1=bcast2(f1);
        const ulonglong2* wp = (const ulonglong2*)&ws[((kh*3+kw)*3+ci)*32];
        #pragma unroll
        for (int q=0;q<8;q++){
          ulonglong2 t=wp[q];
          ffma2(acc[0][2*q],v0,t.x); ffma2(acc[0][2*q+1],v0,t.y);
          ffma2(acc[1][2*q],v1,t.x); ffma2(acc[1][2*q+1],v1,t.y);
        }
      }
    }
  }
  float4* op = (float4*)(g_b1 + (size_t)(2*idx)*32);
  #pragma unroll
  for (int p=0;p<2;p++)
  #pragma unroll
  for (int c4=0;c4<8;c4++){
    float2 a=unpack2(acc[p][2*c4]), b2=unpack2(acc[p][2*c4+1]);
    float4 o; o.x=fmaxf(a.x,0.f); o.y=fmaxf(a.y,0.f); o.z=fmaxf(b2.x,0.f); o.w=fmaxf(b2.y,0.f);
    op[p*8+c4]=o;
  }
}

// ---------------- enc2: 32->64, k3 s2 p1, relu; 2 px/thread, co halves ------
__global__ __launch_bounds__(256) void enc2_k(const float* __restrict__ bias){
  __shared__ __align__(16) float ws[9216];   // [tap][ci=32][co_local=32]
  __shared__ float bs[32];
  int half = blockIdx.y;
  int tid = threadIdx.x;
  for (int i=tid;i<9216;i+=256){
    int c = i & 31; int r = i >> 5;
    ws[i] = g_wr2[r*64 + half*32 + c];
  }
  if (tid<32) bs[tid]=bias[half*32+tid];
  __syncthreads();
  int idx = blockIdx.x*256 + tid;                 // [0, 131072)
  int tw = idx & 31, ho = (idx>>5)&63, b = idx>>11;
  u64 acc[2][16];
  #pragma unroll
  for (int c=0;c<16;c++){ acc[0][c]=pack2(bs[2*c],bs[2*c+1]); acc[1][c]=acc[0][c]; }
  for (int kh=0;kh<3;kh++){
    int hi = 2*ho-1+kh; bool inh = (unsigned)hi<128u;
    for (int kw=0;kw<3;kw++){
      int wi0 = 4*tw-1+kw, wi1 = wi0+2;
      bool in0 = inh && (unsigned)wi0<128u;
      bool in1 = inh && (unsigned)wi1<128u;
      const float4* ip0 = (const float4*)(g_b1 + ((size_t)((b*128+hi)*128+wi0))*32);
      const float4* ip1 = ip0 + 16;   // wi1 = wi0+2 -> +64 floats
      const float* wt = &ws[(kh*3+kw)*1024];
      #pragma unroll 4
      for (int ci4=0;ci4<8;ci4++){
        float4 v0 = in0 ? ip0[ci4] : zero4();
        float4 v1 = in1 ? ip1[ci4] : zero4();
        u64 a0=bcast2(v0.x), a1=bcast2(v0.y), a2=bcast2(v0.z), a3=bcast2(v0.w);
        u64 b0=bcast2(v1.x), b1=bcast2(v1.y), b2=bcast2(v1.z), b3=bcast2(v1.w);
        const ulonglong2* wp = (const ulonglong2*)(wt + ci4*128);
        #pragma unroll
        for (int q=0;q<8;q++){ ulonglong2 t=wp[q];
          ffma2(acc[0][2*q],a0,t.x); ffma2(acc[0][2*q+1],a0,t.y);
          ffma2(acc[1][2*q],b0,t.x); ffma2(acc[1][2*q+1],b0,t.y); }
        #pragma unroll
        for (int q=0;q<8;q++){ ulonglong2 t=wp[8+q];
          ffma2(acc[0][2*q],a1,t.x); ffma2(acc[0][2*q+1],a1,t.y);
          ffma2(acc[1][2*q],b1,t.x); ffma2(acc[1][2*q+1],b1,t.y); }
        #pragma unroll
        for (int q=0;q<8;q++){ ulonglong2 t=wp[16+q];
          ffma2(acc[0][2*q],a2,t.x); ffma2(acc[0][2*q+1],a2,t.y);
          ffma2(acc[1][2*q],b2,t.x); ffma2(acc[1][2*q+1],b2,t.y); }
        #pragma unroll
        for (int q=0;q<8;q++){ ulonglong2 t=wp[24+q];
          ffma2(acc[0][2*q],a3,t.x); ffma2(acc[0][2*q+1],a3,t.y);
          ffma2(acc[1][2*q],b3,t.x); ffma2(acc[1][2*q+1],b3,t.y); }
      }
    }
  }
  #pragma unroll
  for (int p=0;p<2;p++){
    float4* op = (float4*)(g_b2 + (size_t)(2*idx+p)*64 + half*32);
    #pragma unroll
    for (int c4=0;c4<8;c4++){
      float2 a=unpack2(acc[p][2*c4]), b2=unpack2(acc[p][2*c4+1]);
      float4 o; o.x=fmaxf(a.x,0.f); o.y=fmaxf(a.y,0.f); o.z=fmaxf(b2.x,0.f); o.w=fmaxf(b2.y,0.f);
      op[c4]=o;
    }
  }
}

// ------------- enc3 (1x1 64->16) + VQ + quantize + VQ loss; 2 px/thread -----
__global__ __launch_bounds__(256) void vq_k(const float* __restrict__ cb,
                                            const float* __restrict__ w3,
                                            const float* __restrict__ b3){
  __shared__ __align__(16) float cbs[8192];   // [512][16]
  __shared__ float nrm[512];                   // 0.5*||e||^2
  __shared__ __align__(16) float w3s[1024];    // [ci=64][d=16]
  __shared__ float b3s[16];
  int tid = threadIdx.x;
  for (int i=tid;i<8192;i+=256) cbs[i]=cb[i];
  for (int i=tid;i<1024;i+=256){ int ci=i>>4, d=i&15; w3s[i]=w3[d*64+ci]; }
  if (tid<16) b3s[tid]=b3[tid];
  __syncthreads();
  for (int k=tid;k<512;k+=256){
    float s=0.f;
    #pragma unroll
    for (int d=0;d<16;d++){ float e=cbs[k*16+d]; s=fmaf(e,e,s); }
    nrm[k]=0.5f*s;
  }
  __syncthreads();
  int idx = blockIdx.x*256 + tid;                 // [0, 131072)
  u64 z2[2][8];
  #pragma unroll
  for (int q=0;q<8;q++){ z2[0][q]=pack2(b3s[2*q],b3s[2*q+1]); z2[1][q]=z2[0][q]; }
  const float4* ip0 = (const float4*)(g_b2 + (size_t)(2*idx)*64);
  const float4* ip1 = ip0 + 16;
  #pragma unroll 4
  for (int ci4=0;ci4<16;ci4++){
    float4 v0 = ip0[ci4], v1 = ip1[ci4];
    float a[4]={v0.x,v0.y,v0.z,v0.w}, bb[4]={v1.x,v1.y,v1.z,v1.w};
    #pragma unroll
    for (int j=0;j<4;j++){
      u64 vb0 = bcast2(a[j]), vb1 = bcast2(bb[j]);
      const ulonglong2* wp = (const ulonglong2*)&w3s[(ci4*4+j)*16];
      #pragma unroll
      for (int q=0;q<4;q++){ ulonglong2 t=wp[q];
        ffma2(z2[0][2*q],vb0,t.x); ffma2(z2[0][2*q+1],vb0,t.y);
        ffma2(z2[1][2*q],vb1,t.x); ffma2(z2[1][2*q+1],vb1,t.y); }
    }
  }
  int best0=0, best1=0; float bs0=-3.4e38f, bs1=-3.4e38f;
  for (int k=0;k<512;k++){
    const ulonglong2* e2 = (const ulonglong2*)&cbs[k*16];
    ulonglong2 t0=e2[0], t1=e2[1], t2=e2[2], t3=e2[3];
    u64 sa0=0ull, sb0=0ull, sa1=0ull, sb1=0ull;   // 4 independent chains
    ffma2(sa0,z2[0][0],t0.x); ffma2(sb0,z2[0][4],t2.x);
    ffma2(sa1,z2[1][0],t0.x); ffma2(sb1,z2[1][4],t2.x);
    ffma2(sa0,z2[0][1],t0.y); ffma2(sb0,z2[0][5],t2.y);
    ffma2(sa1,z2[1][1],t0.y); ffma2(sb1,z2[1][5],t2.y);
    ffma2(sa0,z2[0][2],t1.x); ffma2(sb0,z2[0][6],t3.x);
    ffma2(sa1,z2[1][2],t1.x); ffma2(sb1,z2[1][6],t3.x);
    ffma2(sa0,z2[0][3],t1.y); ffma2(sb0,z2[0][7],t3.y);
    ffma2(sa1,z2[1][3],t1.y); ffma2(sb1,z2[1][7],t3.y);
    float2 pa0=unpack2(sa0), pb0=unpack2(sb0);
    float2 pa1=unpack2(sa1), pb1=unpack2(sb1);
    float nk = nrm[k];
    float s0 = (pa0.x + pa0.y) + (pb0.x + pb0.y) - nk;
    float s1 = (pa1.x + pa1.y) + (pb1.x + pb1.y) - nk;
    if (s0>bs0){ bs0=s0; best0=k; }
    if (s1>bs1){ bs1=s1; best1=k; }
  }
  float ls=0.f;
  int bests[2]={best0,best1};
  #pragma unroll
  for (int p=0;p<2;p++){
    const float* e = &cbs[bests[p]*16];
    float4* qo = (float4*)(g_q + (size_t)(2*idx+p)*16);
    #pragma unroll
    for (int d4=0;d4<4;d4++){
      float4 o; o.x=e[d4*4+0]; o.y=e[d4*4+1]; o.z=e[d4*4+2]; o.w=e[d4*4+3];
      qo[d4]=o;
      float2 za=unpack2(z2[p][d4*2]), zb=unpack2(z2[p][d4*2+1]);
      float d0=o.x-za.x, d1=o.y-za.y, d2=o.z-zb.x, d3=o.w-zb.y;
      ls = fmaf(d0,d0, fmaf(d1,d1, fmaf(d2,d2, fmaf(d3,d3, ls))));
    }
  }
  float s = blockReduceSum(ls);
  if (tid==0) atomicAdd(&g_acc[0], (double)s);
}

// ------------- dec1: convT 16->64 k3 s2 p1 op1, relu; parity + halves + 2px -
template<int PH,int PW>
__global__ __launch_bounds__(256) void dec1_k(const float* __restrict__ bias){
  constexpr int NKH = PH?2:1, NKW = PW?2:1;
  __shared__ __align__(16) float ws[NKH*NKW*512];  // [tap][ci=16][co_half=32]
  __shared__ float bs[32];
  int half = blockIdx.y;
  int tid = threadIdx.x;
  for (int i=tid;i<NKH*NKW*512;i+=256){
    int j = i & 511; int t = i >> 9;
    int a = t / NKW, c = t % NKW;
    int kh = PH ? a*2 : 1;
    int kw = PW ? c*2 : 1;
    ws[i] = g_wrd1[(kh*3+kw)*1024 + (j>>5)*64 + half*32 + (j&31)];
  }
  if (tid<32) bs[tid]=bias[half*32+tid];
  __syncthreads();
  int idx = blockIdx.x*256 + tid;                 // [0, 131072)
  int tw = idx & 31, hb = (idx>>5)&63, b = idx>>11;
  int wb0 = 2*tw;
  int ho = 2*hb+PH, wo0 = 2*wb0+PW;
  u64 acc[2][16];
  #pragma unroll
  for (int c=0;c<16;c++){ acc[0][c]=pack2(bs[2*c],bs[2*c+1]); acc[1][c]=acc[0][c]; }
  #pragma unroll
  for (int a=0;a<NKH;a++){
    int hi = PH ? (a==0 ? hb+1 : hb) : hb;
    bool inh = PH ? (hi<64) : true;
    #pragma unroll
    for (int cc=0;cc<NKW;cc++){
      int wi0 = PW ? (cc==0 ? wb0+1 : wb0) : wb0;
      int wi1 = wi0+1;
      bool in0 = inh;                     // wi0 <= 63 always
      bool in1 = inh && (wi1<64);
      const float4* ip0 = (const float4*)(g_q + ((size_t)((b*64+hi)*64+wi0))*16);
      const float4* ip1 = ip0 + 4;
      const float* wt = &ws[(a*NKW+cc)*512];
      #pragma unroll
      for (int ci4=0;ci4<4;ci4++){
        float4 v0 = in0 ? ip0[ci4] : zero4();
        float4 v1 = in1 ? ip1[ci4] : zero4();
        float va[4]={v0.x,v0.y,v0.z,v0.w}, vb[4]={v1.x,v1.y,v1.z,v1.w};
        #pragma unroll
        for (int j=0;j<4;j++){
          u64 p0 = bcast2(va[j]), p1 = bcast2(vb[j]);
          const ulonglong2* wp = (const ulonglong2*)(wt + (ci4*4+j)*32);
          #pragma unroll
          for (int q=0;q<8;q++){ ulonglong2 t3=wp[q];
            ffma2(acc[0][2*q],p0,t3.x); ffma2(acc[0][2*q+1],p0,t3.y);
            ffma2(acc[1][2*q],p1,t3.x); ffma2(acc[1][2*q+1],p1,t3.y); }
        }
      }
    }
  }
  #pragma unroll
  for (int p=0;p<2;p++){
    int wo = wo0 + 2*p;
    float4* op = (float4*)(g_d1 + ((size_t)((b*128+ho)*128+wo))*64 + half*32);
    #pragma unroll
    for (int c4=0;c4<8;c4++){
      float2 a=unpack2(acc[p][2*c4]), b2=unpack2(acc[p][2*c4+1]);
      float4 o; o.x=fmaxf(a.x,0.f); o.y=fmaxf(a.y,0.f); o.z=fmaxf(b2.x,0.f); o.w=fmaxf(b2.y,0.f);
      op[c4]=o;
    }
  }
}

// ------------- dec2: convT 64->32 k3 s2 p1 op1, relu; parity + 2px ----------
template<int PH,int PW>
__global__ __launch_bounds__(256) void dec2_k(const float* __restrict__ bias){
  constexpr int NKH = PH?2:1, NKW = PW?2:1;
  __shared__ __align__(16) float ws[NKH*NKW*2048];   // [tap][ci=64][co=32]
  __shared__ float bs[32];
  int tid = threadIdx.x;
  for (int i=tid;i<NKH*NKW*2048;i+=256){
    int j = i & 2047; int t = i >> 11;
    int a = t / NKW, c = t % NKW;
    int kh = PH ? a*2 : 1;
    int kw = PW ? c*2 : 1;
    ws[i] = g_wrd2[(kh*3+kw)*2048 + j];
  }
  if (tid<32) bs[tid]=bias[tid];
  __syncthreads();
  int idx = blockIdx.x*256 + tid;                 // [0, 524288)
  int tw = idx & 63, hb = (idx>>6)&127, b = idx>>13;
  int wb0 = 2*tw;
  int ho = 2*hb+PH, wo0 = 2*wb0+PW;
  u64 acc[2][16];
  #pragma unroll
  for (int c=0;c<16;c++){ acc[0][c]=pack2(bs[2*c],bs[2*c+1]); acc[1][c]=acc[0][c]; }
  #pragma unroll
  for (int a=0;a<NKH;a++){
    int hi = PH ? (a==0 ? hb+1 : hb) : hb;
    bool inh = PH ? (hi<128) : true;
    #pragma unroll
    for (int cc=0;cc<NKW;cc++){
      int wi0 = PW ? (cc==0 ? wb0+1 : wb0) : wb0;
      int wi1 = wi0+1;
      bool in0 = inh;                     // wi0 <= 127 always
      bool in1 = inh && (wi1<128);
      const float4* ip0 = (const float4*)(g_d1 + ((size_t)((b*128+hi)*128+wi0))*64);
      const float4* ip1 = ip0 + 16;
      const float* wt = &ws[(a*NKW+cc)*2048];
      #pragma unroll 4
      for (int ci4=0;ci4<16;ci4++){
        float4 v0 = in0 ? ip0[ci4] : zero4();
        float4 v1 = in1 ? ip1[ci4] : zero4();
        u64 a0=bcast2(v0.x), a1=bcast2(v0.y), a2=bcast2(v0.z), a3=bcast2(v0.w);
        u64 b0=bcast2(v1.x), b1=bcast2(v1.y), b2=bcast2(v1.z), b3=bcast2(v1.w);
        const ulonglong2* wp = (const ulonglong2*)(wt + ci4*128);
        #pragma unroll
        for (int q=0;q<8;q++){ ulonglong2 t=wp[q];
          ffma2(acc[0][2*q],a0,t.x); ffma2(acc[0][2*q+1],a0,t.y);
          ffma2(acc[1][2*q],b0,t.x); ffma2(acc[1][2*q+1],b0,t.y); }
        #pragma unroll
        for (int q=0;q<8;q++){ ulonglong2 t=wp[8+q];
          ffma2(acc[0][2*q],a1,t.x); ffma2(acc[0][2*q+1],a1,t.y);
          ffma2(acc[1][2*q],b1,t.x); ffma2(acc[1][2*q+1],b1,t.y); }
        #pragma unroll
        for (int q=0;q<8;q++){ ulonglong2 t=wp[16+q];
          ffma2(acc[0][2*q],a2,t.x); ffma2(acc[0][2*q+1],a2,t.y);
          ffma2(acc[1][2*q],b2,t.x); ffma2(acc[1][2*q+1],b2,t.y); }
        #pragma unroll
        for (int q=0;q<8;q++){ ulonglong2 t=wp[24+q];
          ffma2(acc[0][2*q],a3,t.x); ffma2(acc[0][2*q+1],a3,t.y);
          ffma2(acc[1][2*q],b3,t.x); ffma2(acc[1][2*q+1],b3,t.y); }
      }
    }
  }
  #pragma unroll
  for (int p=0;p<2;p++){
    int wo = wo0 + 2*p;
    float4* op = (float4*)(g_d2 + ((size_t)((b*256+ho)*256+wo))*32);
    #pragma unroll
    for (int c4=0;c4<8;c4++){
      float2 a=unpack2(acc[p][2*c4]), b2=unpack2(acc[p][2*c4+1]);
      float4 o; o.x=fmaxf(a.x,0.f); o.y=fmaxf(a.y,0.f); o.z=fmaxf(b2.x,0.f); o.w=fmaxf(b2.y,0.f);
      op[c4]=o;
    }
  }
}

// ------------- dec3: convT 32->3 k3 s1 p1 + recon MSE (fused, no store) -----
#define COMPSEL(v,c) ((c)==0 ? (v).x : (c)==1 ? (v).y : (c)==2 ? (v).z : (v).w)
__global__ __launch_bounds__(256) void dec3_k(const float* __restrict__ x,
                                              const float* __restrict__ bias){
  __shared__ __align__(16) u64 ws2[864];    // [kh][kw][ci=32][co=3], dup-pair {w,w}
  __shared__ float bs[3];
  int tid = threadIdx.x;
  for (int i=tid;i<864;i+=256){ float w=g_wrd3[i]; ws2[i]=pack2(w,w); }
  if (tid<3) bs[tid]=bias[tid];
  __syncthreads();
  int idx = blockIdx.x*256 + tid;                 // 64*256*64 (4 pixels/thread in w)
  int tw = idx & 63, ho = (idx>>6)&255, b = idx>>14;
  int wo0 = tw*4;
  u64 accp[3][2];   // [co][pixel-pair]
  #pragma unroll
  for (int co=0;co<3;co++){ accp[co][0]=pack2(bs[co],bs[co]); accp[co][1]=accp[co][0]; }
  for (int kh=0;kh<3;kh++){
    int hi = ho-1+kh; if ((unsigned)hi>=256u) continue;
    const float* rowp = g_d2 + ((size_t)(b*256+hi))*256*32;
    #pragma unroll 2
    for (int ci4=0;ci4<8;ci4++){
      float4 v[6];
      #pragma unroll
      for (int j=0;j<6;j++){
        int wi = wo0-1+j;
        if ((unsigned)wi<256u) v[j] = ((const float4*)(rowp + (size_t)wi*32))[ci4];
        else v[j] = zero4();
      }
      #pragma unroll
      for (int kw=0;kw<3;kw++){
        #pragma unroll
        for (int c=0;c<4;c++){
          float f0=COMPSEL(v[kw+0],c), f1=COMPSEL(v[kw+1],c);
          float f2=COMPSEL(v[kw+2],c), f3=COMPSEL(v[kw+3],c);
          u64 a0=pack2(f0,f1), a1=pack2(f2,f3);
          const u64* wd = &ws2[((kh*3+kw)*32 + ci4*4 + c)*3];
          u64 w0=wd[0], w1=wd[1], w2=wd[2];
          ffma2(accp[0][0],a0,w0); ffma2(accp[0][1],a1,w0);
          ffma2(accp[1][0],a0,w1); ffma2(accp[1][1],a1,w1);
          ffma2(accp[2][0],a0,w2); ffma2(accp[2][1],a1,w2);
        }
      }
    }
  }
  float acc[4][3];
  #pragma unroll
  for (int co=0;co<3;co++){
    float2 p0=unpack2(accp[co][0]), p1=unpack2(accp[co][1]);
    acc[0][co]=p0.x; acc[1][co]=p0.y; acc[2][co]=p1.x; acc[3][co]=p1.y;
  }
  float ls=0.f;
  const float* xb = x + (size_t)b*3*65536;
  #pragma unroll
  for (int o=0;o<4;o++){
    #pragma unroll
    for (int c=0;c<3;c++){
      float d = acc[o][c] - xb[(size_t)c*65536 + ho*256 + wo0+o];
      ls = fmaf(d,d,ls);
    }
  }
  float s = blockReduceSum(ls);
  if (tid==0) atomicAdd(&g_acc[1], (double)s);
}

// ------------- finalize -----------------------------------------------------
__global__ void final_k(float* __restrict__ out){
  double vq  = g_acc[0];
  double rec = g_acc[1];
  float e_q  = (float)(1.25 * vq / 4194304.0);
  float mse  = (float)(rec / 12582912.0);
  out[0] = e_q;
  out[1] = mse;
  out[2] = mse;
}

// ---------------- launch ----------------------------------------------------
extern "C" void kernel_launch(void* const* d_in, const int* in_sizes, int n_in,
                              void* d_out, int out_size){
  const float* x   = (const float*)d_in[0];
  const float* ew1 = (const float*)d_in[1];
  const float* eb1 = (const float*)d_in[2];
  const float* ew2 = (const float*)d_in[3];
  const float* eb2 = (const float*)d_in[4];
  const float* ew3 = (const float*)d_in[5];
  const float* eb3 = (const float*)d_in[6];
  const float* cb  = (const float*)d_in[7];
  const float* dw1 = (const float*)d_in[8];
  const float* db1 = (const float*)d_in[9];
  const float* dw2 = (const float*)d_in[10];
  const float* db2 = (const float*)d_in[11];
  const float* dw3 = (const float*)d_in[12];
  const float* db3 = (const float*)d_in[13];
  float* out = (float*)d_out;

  repack_k<<<64,256>>>(ew1, ew2, dw1, dw2, dw3);
  enc1_k<<<2048,256>>>(x, eb1);
  enc2_k<<<dim3(512,2),256>>>(eb2);
  vq_k<<<512,256>>>(cb, ew3, eb3);
  dec1_k<0,0><<<dim3(512,2),256>>>(db1);
  dec1_k<0,1><<<dim3(512,2),256>>>(db1);
  dec1_k<1,0><<<dim3(512,2),256>>>(db1);
  dec1_k<1,1><<<dim3(512,2),256>>>(db1);
  dec2_k<0,0><<<2048,256>>>(db2);
  dec2_k<0,1><<<2048,256>>>(db2);
  dec2_k<1,0><<<2048,256>>>(db2);
  dec2_k<1,1><<<2048,256>>>(db2);
  dec3_k<<<4096,256>>>(x, db3);
  final_k<<<1,1>>>(out);
}